// round 13
// baseline (speedup 1.0000x reference)
#include <cuda_runtime.h>
#include <math.h>

#define KK 16
#define TT 40
#define BB 16
#define NN 32
#define BN 512
#define KBN 8192
#define HH2 80
#define C1 16
#define C2 32
#define NBIN 36
#define NBLK 144
#define TSC 512

typedef unsigned long long ull;

__device__ float g_conv1[BB*C1*HH2*HH2];
__device__ float g_fmap [BB*HH2*HH2*C2];
__device__ float g_lhalf[KK*TT*BN*48];
__device__ int   g_cnt[KK*TT*BN];
__device__ float2 g_ent[(size_t)KK*TT*BN*32];
__device__ float g_HW [BB*NN*NBIN*48];
__device__ float g_h0 [2][BN*48];
__device__ float g_hfin[KBN*48];
__device__ float g_score[KBN];
__device__ unsigned g_cnt8[8];
__device__ unsigned g_bar_flag;

// ---- f32x2 / fast-math helpers ----
__device__ __forceinline__ ull pk2(float lo, float hi) {
    ull r; asm("mov.b64 %0, {%1,%2};" : "=l"(r) : "f"(lo), "f"(hi)); return r;
}
__device__ __forceinline__ void upk2(ull v, float& lo, float& hi) {
    asm("mov.b64 {%0,%1}, %2;" : "=f"(lo), "=f"(hi) : "l"(v));
}
__device__ __forceinline__ void fma2(ull& a, ull x, ull y) {
    asm("fma.rn.f32x2 %0, %1, %2, %0;" : "+l"(a) : "l"(x), "l"(y));
}
__device__ __forceinline__ float sigf(float x) {
    float e; asm("ex2.approx.f32 %0, %1;" : "=f"(e) : "f"(x * -1.4426950408889634f));
    float r; asm("rcp.approx.f32 %0, %1;" : "=f"(r) : "f"(1.f + e));
    return r;
}
__device__ __forceinline__ float tanh_fast(float x) { return 2.f*sigf(2.f*x) - 1.f; }

// ---------------- bins helper ----------------
__device__ __forceinline__ int bin_of(float dx, float dy) {
    float dist = sqrtf(dx*dx + dy*dy);
    float dc = dist < 1e-10f ? 1e-10f : dist;
    float ct = acosf(fminf(fmaxf(dx/dc, -1.f), 1.f));
    float theta = (dy < -0.01f) ? (6.2831853071795864f - ct) : ct;
    const float R_STEP  = (float)(3.5/6.0);
    const float TH_STEP = (float)(6.283185307179586/6.0);
    int ub = (int)((dist - 0.5f)/R_STEP); ub = min(max(ub,0),5);
    int vb = (int)(theta/TH_STEP);        vb = min(max(vb,0),5);
    return ub*6 + vb;
}

// ---------------- conv1 + bins + init (merged) ----------------
__global__ void conv1x_kernel(const float* __restrict__ img,
                              const float* __restrict__ w,
                              const float* __restrict__ bias,
                              const float* __restrict__ y_path,
                              const float* __restrict__ hx) {
    __shared__ float sW[1600];
    __shared__ float sB[16];
    __shared__ float sP[8][NN][2];
    int blk = blockIdx.x, tid = threadIdx.x;
    if (blk < 6400) {
        for (int i = tid; i < 1600; i += 256) sW[i] = w[i];
        if (tid < 16) sB[tid] = bias[tid];
        __syncthreads();
        int idx = blk*256 + tid;
        int x = idx % HH2; int y = (idx/HH2) % HH2;
        int oc = (idx/(HH2*HH2)) % C1; int b = idx/(HH2*HH2*C1);
        float acc = sB[oc];
        for (int ic = 0; ic < 4; ic++)
            for (int ky = 0; ky < 5; ky++) {
                int iy = 2*y - 2 + ky;
                if (iy < 0 || iy >= 160) continue;
                const float* ip = img + ((b*4+ic)*160 + iy)*160;
                const float* wp = sW + (oc*4+ic)*25 + ky*5;
                #pragma unroll
                for (int kx = 0; kx < 5; kx++) {
                    int ix = 2*x - 2 + kx;
                    if (ix < 0 || ix >= 160) continue;
                    acc += ip[ix] * wp[kx];
                }
            }
        g_conv1[idx] = fmaxf(acc, 0.f);
    } else if (blk < 7680) {
        int g = tid >> 5, j = tid & 31;
        int grp = (blk - 6400)*8 + g;          // 10240 exact
        int b = grp % BB; int kt = grp / BB;
        int rowbase = kt*BN + b*NN;
        sP[g][j][0] = y_path[(rowbase+j)*2];
        sP[g][j][1] = y_path[(rowbase+j)*2+1];
        __syncwarp();
        float pjx = sP[g][j][0], pjy = sP[g][j][1];
        unsigned maskbits = 0;
        #pragma unroll
        for (int n2 = 0; n2 < NN; n2++) {
            float dx = sP[g][n2][0] - pjx;
            float dy = sP[g][n2][1] - pjy;
            float dist = sqrtf(dx*dx + dy*dy);
            if (n2 != j && dist >= 0.5f && dist <= 4.0f) maskbits |= 1u << n2;
        }
        size_t rowid = rowbase + j;
        int e = 0;
        unsigned m1 = maskbits;
        while (m1) {
            int n2 = __ffs(m1) - 1; m1 &= m1 - 1;
            int bn = bin_of(sP[g][n2][0]-pjx, sP[g][n2][1]-pjy);
            int cnt = 0;
            unsigned mq = maskbits;
            while (mq) {
                int q = __ffs(mq) - 1; mq &= mq - 1;
                cnt += (bin_of(sP[g][q][0]-pjx, sP[g][q][1]-pjy) == bn);
            }
            g_ent[rowid*32 + e] = make_float2(1.f/(float)cnt,
                                __int_as_float((n2*NBIN + bn)*48));
            e++;
        }
        g_cnt[rowid] = e;
    } else {
        int idx = (blk - 7680)*256 + tid;      // 24576 exact
        g_h0[0][idx] = hx[idx];
        if (idx < 8) g_cnt8[idx] = 0u;
        if (idx == 0) g_bar_flag = 0u;
    }
}

// ---------------- conv2 (f32x2) ----------------
__global__ void conv2_kernel(const float* __restrict__ w2,
                             const float* __restrict__ b2) {
    __shared__ float sIn[6400];
    __shared__ __align__(16) float sW[3200];
    int blk = blockIdx.x;                       // 1600
    int ocg = blk % 4; int tile = (blk/4) % 25; int b = blk/100;
    int ty0 = (tile/5)*16, tx0 = (tile%5)*16;
    int tid = threadIdx.x;                      // 128
    for (int i = tid; i < 6400; i += 128) {
        int ic = i/400; int rem = i%400; int ly = rem/20, lx = rem%20;
        int iy = ty0 + ly - 2, ix = tx0 + lx - 2;
        sIn[i] = (iy>=0 && iy<HH2 && ix>=0 && ix<HH2)
                 ? g_conv1[((b*C1+ic)*HH2+iy)*HH2+ix] : 0.f;
    }
    for (int i = tid; i < 3200; i += 128) {
        int ic = i/200, rem = i%200, k2 = rem/8, ocl = rem%8;
        sW[i] = w2[(ocg*8+ocl)*400 + ic*25 + k2];
    }
    __syncthreads();
    int tx = tid % 16, tyh = tid / 16;
    ull a0[4], a1[4];
    #pragma unroll
    for (int o2 = 0; o2 < 4; o2++) {
        a0[o2] = pk2(b2[ocg*8+2*o2], b2[ocg*8+2*o2+1]);
        a1[o2] = a0[o2];
    }
    for (int ic = 0; ic < 16; ic++) {
        float in0[25], in1[25];
        const float* p0 = sIn + ic*400 + tyh*20 + tx;
        const float* p1 = p0 + 160;
        #pragma unroll
        for (int ky = 0; ky < 5; ky++)
            #pragma unroll
            for (int kx = 0; kx < 5; kx++) {
                in0[ky*5+kx] = p0[ky*20+kx];
                in1[ky*5+kx] = p1[ky*20+kx];
            }
        #pragma unroll
        for (int k2 = 0; k2 < 25; k2++) {
            ull i0 = pk2(in0[k2], in0[k2]);
            ull i1 = pk2(in1[k2], in1[k2]);
            const float* wb = &sW[(ic*25+k2)*8];
            #pragma unroll
            for (int o2 = 0; o2 < 4; o2++) {
                ull w = *(const ull*)(wb + 2*o2);
                fma2(a0[o2], i0, w); fma2(a1[o2], i1, w);
            }
        }
    }
    #pragma unroll
    for (int o2 = 0; o2 < 4; o2++) {
        float v0, v1, u0, u1;
        upk2(a0[o2], v0, v1); upk2(a1[o2], u0, u1);
        int oc = ocg*8 + 2*o2;
        float* d0 = &g_fmap[((b*HH2 + ty0+tyh  )*HH2 + tx0+tx)*C2 + oc];
        float* d1 = &g_fmap[((b*HH2 + ty0+tyh+8)*HH2 + tx0+tx)*C2 + oc];
        d0[0] = fmaxf(v0, 0.f); d0[1] = fmaxf(v1, 0.f);
        d1[0] = fmaxf(u0, 0.f); d1[1] = fmaxf(u1, 0.f);
    }
}

// ---------------- lhalf ----------------
__global__ void lhalf_kernel(const float* __restrict__ y_path,
                             const float* __restrict__ cur_loc,
                             const float* __restrict__ fvw,
                             const float* __restrict__ fvb) {
    int idx = blockIdx.x*256 + threadIdx.x;    // 7,864,320
    int cp = idx % 24; int row = idx / 24;
    int kt = row / BN, i2 = row % BN;
    int t = kt % TT; int b = i2 >> 5;
    float px = y_path[row*2], py = y_path[row*2+1];
    float2 out;
    if (cp < 16) {
        int u = 40 - (int)py; u = min(max(u,0), HH2-1);
        int v = (int)px;      v = min(max(v,0), HH2-1);
        out = *(const float2*)&g_fmap[((b*HH2+u)*HH2+v)*C2 + 2*cp];
    } else {
        int cc = 2*cp - 32;
        float pvx, pvy;
        if (t == 0) { pvx = cur_loc[i2*2]; pvy = cur_loc[i2*2+1]; }
        else { pvx = y_path[(row-BN)*2]; pvy = y_path[(row-BN)*2+1]; }
        float vx = (px-pvx)*10.f, vy = (py-pvy)*10.f;
        out.x = fvb[cc]   + vx*fvw[cc*2]   + vy*fvw[cc*2+1];
        out.y = fvb[cc+1] + vx*fvw[cc*2+2] + vy*fvw[cc*2+3];
    }
    *(float2*)&g_lhalf[(size_t)idx*2] = out;
}

// ---------------- two-level grid barrier ----------------
__device__ __forceinline__ void gbar(unsigned target, int blk) {
    __syncthreads();
    if (threadIdx.x == 0) {
        asm volatile("red.release.gpu.global.add.u32 [%0], 1;"
                     :: "l"(&g_cnt8[blk & 7]) : "memory");
        if (blk == 0) {
            unsigned s;
            do {
                s = 0;
                #pragma unroll
                for (int i = 0; i < 8; i++) {
                    unsigned v;
                    asm volatile("ld.acquire.gpu.global.u32 %0, [%1];"
                                 : "=r"(v) : "l"(&g_cnt8[i]) : "memory");
                    s += v;
                }
            } while (s < target * (unsigned)NBLK);
            asm volatile("st.release.gpu.global.u32 [%0], %1;"
                         :: "l"(&g_bar_flag), "r"(target) : "memory");
        } else {
            unsigned v;
            do {
                __nanosleep(20);
                asm volatile("ld.acquire.gpu.global.u32 %0, [%1];"
                             : "=r"(v) : "l"(&g_bar_flag) : "memory");
            } while (v < target);
        }
    }
    __syncthreads();
}

// ---------------- persistent fused scan ----------------
__global__ void __launch_bounds__(TSC, 1) scan_kernel(
        const float* __restrict__ hx,   const float* __restrict__ scfw,
        const float* __restrict__ whh,  const float* __restrict__ bhh,
        const float* __restrict__ wih,  const float* __restrict__ bih,
        const float* __restrict__ scfb, const float* __restrict__ scw) {
    extern __shared__ float sm[];
    float* sWT  = sm;              // 9216  Wscf og-slice (oo,hh,c)
    float* sWih = sm + 9216;       // 13920 (96 x 145)
    float* sWhh = sm + 23136;      // 6960  (48 x 145)
    float* sBi  = sm + 30096;      // 144
    float* sBh  = sm + 30240;      // 144
    float* sFb  = sm + 30384;      // 48
    float* sScw = sm + 30432;      // 48
    float* sHnT = sm + 30480;      // 1584 (48 x 33)
    float* sLT  = sm + 32064;      // 3168 (48 x 66) lhalf^T
    float* sRT  = sm + 35232;      // 3168 rhalf^T
    float* sBufA= sm + 38400;      // 3168 h^T ping
    float* sBufB= sm + 41568;      // 3168 h^T pong
    float2* sEnt = (float2*)(sm + 44736);  // 4096 fl (64 x 32 float2)
    int*   sCnt = (int*)(sm + 48832);      // 64
    float* sSc  = sm + 48896;      // 1536
    float* sScA = sm + 50432;      // 64 -> total 50496 fl

    int tid = threadIdx.x, blk = blockIdx.x;
    int bA = blk / 9, og = blk % 9;
    bool rowRole = (blk < 128);
    int r0 = blk * 64;
    int kq = r0 >> 9, i2b = r0 & 511;

    for (int i = tid; i < 9216; i += TSC) {
        int c = i % 48, rest = i / 48, hh = rest % 48, oo = rest / 48;
        sWT[oo*2304 + hh*48 + c] = scfw[c*1728 + (og*4+oo)*48 + hh];
    }
    for (int i = tid; i < 13824; i += TSC) {
        int c = i / 96, m = i % 96;
        sWih[m*145 + c] = wih[i];
    }
    for (int i = tid; i < 6912; i += TSC) {
        int c = i / 48, m = i % 48;
        sWhh[m*145 + c] = whh[i];
    }
    if (tid < 144) { sBi[tid] = bih[tid]; sBh[tid] = bhh[tid]; }
    if (tid < 48)  { sFb[tid] = scfb[tid]; sScw[tid] = scw[tid]; }
    if (tid < 64)  sScA[tid] = 0.f;
    float* pH = sBufA;
    float* pN = sBufB;
    if (rowRole)
        for (int i = tid; i < 3072; i += TSC) {
            int row = i / 48, c = i % 48;
            pH[c*66 + row] = hx[(i2b + row)*48 + c];
        }
    __syncthreads();

    unsigned bar = 0;
    for (int t = 0; t < TT; t++) {
        // ---- h0 slice (needed for HW now) ----
        const float* hsrc = g_h0[t & 1] + bA*1536;
        for (int i = tid; i < 1536; i += TSC) {
            int n2 = i / 48, hh = i % 48;
            sHnT[hh*33 + n2] = __ldcg(hsrc + i);
        }
        __syncthreads();
        // ---- static loads for this step; land during HW compute ----
        int gb = 0;
        if (rowRole) {
            gb = (kq*TT + t)*BN + i2b;
            for (int i = tid; i < 3072; i += TSC) {
                int row = i / 48, c = i % 48;
                sLT[c*66 + row] = g_lhalf[(size_t)gb*48 + i];
            }
            if (tid < 64) {
                int cnt = g_cnt[gb + tid];
                sCnt[tid] = cnt;
                for (int e = 0; e < cnt; e++)
                    sEnt[tid*32 + e] = g_ent[(size_t)(gb + tid)*32 + e];
            }
        }
        // ---- HW table slice ----
        for (int it = tid; it < 768; it += TSC) {
            int cg = it % 24, oo = (it/24) & 3, n2g = it / 96;
            float a0[4], a1[4];
            #pragma unroll
            for (int i = 0; i < 4; i++) { a0[i] = 0.f; a1[i] = 0.f; }
            const float* wt = sWT + oo*2304;
            for (int hh = 0; hh < 48; hh++) {
                float w0 = wt[hh*48 + cg], w1 = wt[hh*48 + cg + 24];
                #pragma unroll
                for (int i = 0; i < 4; i++) {
                    float hv = sHnT[hh*33 + n2g*4 + i];
                    a0[i] += hv*w0; a1[i] += hv*w1;
                }
            }
            #pragma unroll
            for (int i = 0; i < 4; i++) {
                int base = ((bA*NN + n2g*4+i)*NBIN + og*4 + oo)*48;
                g_HW[base + cg]      = a0[i];
                g_HW[base + cg + 24] = a1[i];
            }
        }
        gbar(++bar, blk);
        if (rowRole) {
            // ---- gather ----
            for (int out = tid; out < 3072; out += TSC) {
                int lr = out / 48, c = out % 48;
                int cnt = sCnt[lr];
                float acc = sFb[c];
                const float* hwb = g_HW + ((i2b + lr) >> 5)*(NN*NBIN*48);
                for (int e = 0; e < cnt; e++) {
                    float2 en = sEnt[lr*32 + e];
                    acc += en.x * __ldcg(hwb + __float_as_int(en.y) + c);
                }
                sRT[c*66 + lr] = acc;
            }
            __syncthreads();
            // ---- fused f32x2 GEMM (4-row x 2-col tiles, 384 threads) ----
            if (tid < 384) {
                int cg = tid % 24, rg = tid / 24, rl = rg*4;
                ull gr2[2][2], gz2[2][2], gnx2[2][2], gnh2[2][2];
                #pragma unroll
                for (int jj = 0; jj < 2; jj++) {
                    int c = cg + 24*jj;
                    ull t0;
                    t0 = pk2(sBi[c]+sBh[c],       sBi[c]+sBh[c]);
                    gr2[0][jj] = t0; gr2[1][jj] = t0;
                    t0 = pk2(sBi[48+c]+sBh[48+c], sBi[48+c]+sBh[48+c]);
                    gz2[0][jj] = t0; gz2[1][jj] = t0;
                    t0 = pk2(sBi[96+c], sBi[96+c]);
                    gnx2[0][jj] = t0; gnx2[1][jj] = t0;
                    t0 = pk2(sBh[96+c], sBh[96+c]);
                    gnh2[0][jj] = t0; gnh2[1][jj] = t0;
                }
                #define SEG(XS, WP, NACC)                                      \
                for (int m = 0; m < 48; m++) {                                 \
                    ull x0 = *(const ull*)&XS[m*66 + rl];                      \
                    ull x1 = *(const ull*)&XS[m*66 + rl + 2];                  \
                    const float* wp = WP + m*145;                              \
                    _Pragma("unroll")                                          \
                    for (int jj = 0; jj < 2; jj++) {                           \
                        int c = cg + 24*jj;                                    \
                        ull wr = pk2(wp[c], wp[c]);                            \
                        ull wz = pk2(wp[48+c], wp[48+c]);                      \
                        ull wn = pk2(wp[96+c], wp[96+c]);                      \
                        fma2(gr2[0][jj], x0, wr); fma2(gr2[1][jj], x1, wr);    \
                        fma2(gz2[0][jj], x0, wz); fma2(gz2[1][jj], x1, wz);    \
                        fma2(NACC[0][jj], x0, wn); fma2(NACC[1][jj], x1, wn);  \
                    }                                                          \
                }
                SEG(sLT, sWih, gnx2)
                SEG((sRT), (sWih + 48*145), gnx2)
                SEG(pH, sWhh, gnh2)
                #undef SEG
                float scacc[4] = {0.f, 0.f, 0.f, 0.f};
                #pragma unroll
                for (int p = 0; p < 2; p++) {
                    #pragma unroll
                    for (int jj = 0; jj < 2; jj++) {
                        int c = cg + 24*jj;
                        float grl, grh, gzl, gzh, gxl, gxh, ghl, ghh;
                        upk2(gr2[p][jj],  grl, grh);
                        upk2(gz2[p][jj],  gzl, gzh);
                        upk2(gnx2[p][jj], gxl, gxh);
                        upk2(gnh2[p][jj], ghl, ghh);
                        int rowl = rl + 2*p, rowh = rowl + 1;
                        float r0f = sigf(grl), z0f = sigf(gzl);
                        float n0f = tanh_fast(gxl + r0f*ghl);
                        float h0f = (1.f - z0f)*n0f + z0f*pH[c*66 + rowl];
                        pN[c*66 + rowl] = h0f;
                        scacc[2*p]   += h0f * sScw[c];
                        float r1f = sigf(grh), z1f = sigf(gzh);
                        float n1f = tanh_fast(gxh + r1f*ghh);
                        float h1f = (1.f - z1f)*n1f + z1f*pH[c*66 + rowh];
                        pN[c*66 + rowh] = h1f;
                        scacc[2*p+1] += h1f * sScw[c];
                    }
                }
                #pragma unroll
                for (int i = 0; i < 4; i++) sSc[(rl+i)*24 + cg] = scacc[i];
            }
            __syncthreads();
            if (tid < 64) {
                float s = 0.f;
                #pragma unroll
                for (int c = 0; c < 24; c++) s += sSc[tid*24 + c];
                sScA[tid] += s;
            }
            if (blk < 8) {
                float* dst = g_h0[1 - (t & 1)] + r0*48;
                for (int i = tid; i < 3072; i += TSC) {
                    int row = i / 48, c = i % 48;
                    dst[i] = pN[c*66 + row];
                }
            }
        }
        { float* tmp = pH; pH = pN; pN = tmp; }
        gbar(++bar, blk);
    }
    if (rowRole) {
        for (int i = tid; i < 3072; i += TSC) {
            int row = i / 48, c = i % 48;
            g_hfin[(size_t)r0*48 + i] = pH[c*66 + row];
        }
        if (tid < 64) g_score[r0 + tid] = sScA[tid];
    }
}

// ---------------- final ----------------
__global__ void final_kernel(const float* __restrict__ dyw,
                             const float* __restrict__ dyb,
                             const float* __restrict__ scb,
                             float* __restrict__ out) {
    int idx = blockIdx.x*256 + threadIdx.x;    // 663552
    if (idx < KBN*80) {
        int row = idx / 80, c = idx % 80;
        float acc = dyb[c];
        const float* hr = g_hfin + row*48;
        const float* w  = dyw + c*48;
        #pragma unroll 8
        for (int hh = 0; hh < 48; hh++) acc += hr[hh]*w[hh];
        int k = row >> 9, i2 = row & 511;
        int d = c / 40, tt = c % 40;
        out[((k*TT + tt)*BN + i2)*2 + d] = acc;
    } else {
        int row = idx - KBN*80;
        out[KBN*80 + row] = g_score[row] + 40.f*scb[0];
    }
}

// ---------------- launcher ----------------
extern "C" void kernel_launch(void* const* d_in, const int* in_sizes, int n_in,
                              void* d_out, int out_size) {
    const float* hx      = (const float*)d_in[0];
    const float* cur_loc = (const float*)d_in[1];
    const float* y_path  = (const float*)d_in[2];
    const float* image   = (const float*)d_in[3];
    const float* c1w     = (const float*)d_in[4];
    const float* c1b     = (const float*)d_in[5];
    const float* c2w     = (const float*)d_in[6];
    const float* c2b     = (const float*)d_in[7];
    const float* fvw     = (const float*)d_in[8];
    const float* fvb     = (const float*)d_in[9];
    const float* scfw    = (const float*)d_in[10];
    const float* scfb    = (const float*)d_in[11];
    const float* wih     = (const float*)d_in[12];
    const float* whh     = (const float*)d_in[13];
    const float* bih     = (const float*)d_in[14];
    const float* bhh     = (const float*)d_in[15];
    const float* dyw     = (const float*)d_in[16];
    const float* dyb     = (const float*)d_in[17];
    const float* scw     = (const float*)d_in[18];
    const float* scb     = (const float*)d_in[19];

    const int SMEM_SCAN = 50496 * 4;           // 201984 B
    cudaFuncSetAttribute(scan_kernel,
                         cudaFuncAttributeMaxDynamicSharedMemorySize, SMEM_SCAN);

    conv1x_kernel<<<7776, 256>>>(image, c1w, c1b, y_path, hx);
    conv2_kernel <<<1600, 128>>>(c2w, c2b);
    lhalf_kernel <<<30720,256>>>(y_path, cur_loc, fvw, fvb);
    scan_kernel  <<<NBLK, TSC, SMEM_SCAN>>>(hx, scfw, whh, bhh, wih, bih, scfb, scw);
    final_kernel <<<2592, 256>>>(dyw, dyb, scb, (float*)d_out);
}

// round 14
// speedup vs baseline: 1.0882x; 1.0882x over previous
#include <cuda_runtime.h>
#include <math.h>

#define KK 16
#define TT 40
#define BB 16
#define NN 32
#define BN 512
#define KBN 8192
#define HH2 80
#define C1 16
#define C2 32
#define NBIN 36
#define NBLK 144
#define TSC 512
#define HWSZ (BB*NN*NBIN*48)

typedef unsigned long long ull;

__device__ float g_conv1[BB*C1*HH2*HH2];
__device__ float g_fmap [BB*HH2*HH2*C2];
__device__ float g_lhalf[KK*TT*BN*48];
__device__ int   g_cnt[KK*TT*BN];
__device__ float2 g_ent[(size_t)KK*TT*BN*32];
__device__ float g_HW [2][HWSZ];
__device__ float g_h0 [2][BN*48];
__device__ float g_hfin[KBN*48];
__device__ float g_score[KBN];
__device__ unsigned g_bar_count;
__device__ unsigned g_bar_flag;
__device__ unsigned g_h0cnt;

// ---- f32x2 / fast-math helpers ----
__device__ __forceinline__ ull pk2(float lo, float hi) {
    ull r; asm("mov.b64 %0, {%1,%2};" : "=l"(r) : "f"(lo), "f"(hi)); return r;
}
__device__ __forceinline__ void upk2(ull v, float& lo, float& hi) {
    asm("mov.b64 {%0,%1}, %2;" : "=f"(lo), "=f"(hi) : "l"(v));
}
__device__ __forceinline__ void fma2(ull& a, ull x, ull y) {
    asm("fma.rn.f32x2 %0, %1, %2, %0;" : "+l"(a) : "l"(x), "l"(y));
}
__device__ __forceinline__ float sigf(float x) {
    float e; asm("ex2.approx.f32 %0, %1;" : "=f"(e) : "f"(x * -1.4426950408889634f));
    float r; asm("rcp.approx.f32 %0, %1;" : "=f"(r) : "f"(1.f + e));
    return r;
}
__device__ __forceinline__ float tanh_fast(float x) { return 2.f*sigf(2.f*x) - 1.f; }

// ---------------- bins helper ----------------
__device__ __forceinline__ int bin_of(float dx, float dy) {
    float dist = sqrtf(dx*dx + dy*dy);
    float dc = dist < 1e-10f ? 1e-10f : dist;
    float ct = acosf(fminf(fmaxf(dx/dc, -1.f), 1.f));
    float theta = (dy < -0.01f) ? (6.2831853071795864f - ct) : ct;
    const float R_STEP  = (float)(3.5/6.0);
    const float TH_STEP = (float)(6.283185307179586/6.0);
    int ub = (int)((dist - 0.5f)/R_STEP); ub = min(max(ub,0),5);
    int vb = (int)(theta/TH_STEP);        vb = min(max(vb,0),5);
    return ub*6 + vb;
}

// ---------------- conv1 + bins + init (merged) ----------------
__global__ void conv1x_kernel(const float* __restrict__ img,
                              const float* __restrict__ w,
                              const float* __restrict__ bias,
                              const float* __restrict__ y_path,
                              const float* __restrict__ hx) {
    __shared__ float sW[1600];
    __shared__ float sB[16];
    __shared__ float sP[8][NN][2];
    int blk = blockIdx.x, tid = threadIdx.x;
    if (blk < 6400) {
        for (int i = tid; i < 1600; i += 256) sW[i] = w[i];
        if (tid < 16) sB[tid] = bias[tid];
        __syncthreads();
        int idx = blk*256 + tid;
        int x = idx % HH2; int y = (idx/HH2) % HH2;
        int oc = (idx/(HH2*HH2)) % C1; int b = idx/(HH2*HH2*C1);
        float acc = sB[oc];
        for (int ic = 0; ic < 4; ic++)
            for (int ky = 0; ky < 5; ky++) {
                int iy = 2*y - 2 + ky;
                if (iy < 0 || iy >= 160) continue;
                const float* ip = img + ((b*4+ic)*160 + iy)*160;
                const float* wp = sW + (oc*4+ic)*25 + ky*5;
                #pragma unroll
                for (int kx = 0; kx < 5; kx++) {
                    int ix = 2*x - 2 + kx;
                    if (ix < 0 || ix >= 160) continue;
                    acc += ip[ix] * wp[kx];
                }
            }
        g_conv1[idx] = fmaxf(acc, 0.f);
    } else if (blk < 7680) {
        int g = tid >> 5, j = tid & 31;
        int grp = (blk - 6400)*8 + g;          // 10240 exact
        int b = grp % BB; int kt = grp / BB;
        int rowbase = kt*BN + b*NN;
        sP[g][j][0] = y_path[(rowbase+j)*2];
        sP[g][j][1] = y_path[(rowbase+j)*2+1];
        __syncwarp();
        float pjx = sP[g][j][0], pjy = sP[g][j][1];
        unsigned maskbits = 0;
        #pragma unroll
        for (int n2 = 0; n2 < NN; n2++) {
            float dx = sP[g][n2][0] - pjx;
            float dy = sP[g][n2][1] - pjy;
            float dist = sqrtf(dx*dx + dy*dy);
            if (n2 != j && dist >= 0.5f && dist <= 4.0f) maskbits |= 1u << n2;
        }
        size_t rowid = rowbase + j;
        int e = 0;
        unsigned m1 = maskbits;
        while (m1) {
            int n2 = __ffs(m1) - 1; m1 &= m1 - 1;
            int bn = bin_of(sP[g][n2][0]-pjx, sP[g][n2][1]-pjy);
            int cnt = 0;
            unsigned mq = maskbits;
            while (mq) {
                int q = __ffs(mq) - 1; mq &= mq - 1;
                cnt += (bin_of(sP[g][q][0]-pjx, sP[g][q][1]-pjy) == bn);
            }
            g_ent[rowid*32 + e] = make_float2(1.f/(float)cnt,
                                __int_as_float((n2*NBIN + bn)*48));
            e++;
        }
        g_cnt[rowid] = e;
    } else {
        int idx = (blk - 7680)*256 + tid;      // 24576 exact
        g_h0[0][idx] = hx[idx];
        if (idx == 0) { g_bar_count = 0u; g_bar_flag = 0u; g_h0cnt = 0u; }
    }
}

// ---------------- conv2 (f32x2) ----------------
__global__ void conv2_kernel(const float* __restrict__ w2,
                             const float* __restrict__ b2) {
    __shared__ float sIn[6400];
    __shared__ __align__(16) float sW[3200];
    int blk = blockIdx.x;                       // 1600
    int ocg = blk % 4; int tile = (blk/4) % 25; int b = blk/100;
    int ty0 = (tile/5)*16, tx0 = (tile%5)*16;
    int tid = threadIdx.x;                      // 128
    for (int i = tid; i < 6400; i += 128) {
        int ic = i/400; int rem = i%400; int ly = rem/20, lx = rem%20;
        int iy = ty0 + ly - 2, ix = tx0 + lx - 2;
        sIn[i] = (iy>=0 && iy<HH2 && ix>=0 && ix<HH2)
                 ? g_conv1[((b*C1+ic)*HH2+iy)*HH2+ix] : 0.f;
    }
    for (int i = tid; i < 3200; i += 128) {
        int ic = i/200, rem = i%200, k2 = rem/8, ocl = rem%8;
        sW[i] = w2[(ocg*8+ocl)*400 + ic*25 + k2];
    }
    __syncthreads();
    int tx = tid % 16, tyh = tid / 16;
    ull a0[4], a1[4];
    #pragma unroll
    for (int o2 = 0; o2 < 4; o2++) {
        a0[o2] = pk2(b2[ocg*8+2*o2], b2[ocg*8+2*o2+1]);
        a1[o2] = a0[o2];
    }
    for (int ic = 0; ic < 16; ic++) {
        float in0[25], in1[25];
        const float* p0 = sIn + ic*400 + tyh*20 + tx;
        const float* p1 = p0 + 160;
        #pragma unroll
        for (int ky = 0; ky < 5; ky++)
            #pragma unroll
            for (int kx = 0; kx < 5; kx++) {
                in0[ky*5+kx] = p0[ky*20+kx];
                in1[ky*5+kx] = p1[ky*20+kx];
            }
        #pragma unroll
        for (int k2 = 0; k2 < 25; k2++) {
            ull i0 = pk2(in0[k2], in0[k2]);
            ull i1 = pk2(in1[k2], in1[k2]);
            const float* wb = &sW[(ic*25+k2)*8];
            #pragma unroll
            for (int o2 = 0; o2 < 4; o2++) {
                ull w = *(const ull*)(wb + 2*o2);
                fma2(a0[o2], i0, w); fma2(a1[o2], i1, w);
            }
        }
    }
    #pragma unroll
    for (int o2 = 0; o2 < 4; o2++) {
        float v0, v1, u0, u1;
        upk2(a0[o2], v0, v1); upk2(a1[o2], u0, u1);
        int oc = ocg*8 + 2*o2;
        float* d0 = &g_fmap[((b*HH2 + ty0+tyh  )*HH2 + tx0+tx)*C2 + oc];
        float* d1 = &g_fmap[((b*HH2 + ty0+tyh+8)*HH2 + tx0+tx)*C2 + oc];
        d0[0] = fmaxf(v0, 0.f); d0[1] = fmaxf(v1, 0.f);
        d1[0] = fmaxf(u0, 0.f); d1[1] = fmaxf(u1, 0.f);
    }
}

// ---------------- lhalf ----------------
__global__ void lhalf_kernel(const float* __restrict__ y_path,
                             const float* __restrict__ cur_loc,
                             const float* __restrict__ fvw,
                             const float* __restrict__ fvb) {
    int idx = blockIdx.x*256 + threadIdx.x;    // 7,864,320
    int cp = idx % 24; int row = idx / 24;
    int kt = row / BN, i2 = row % BN;
    int t = kt % TT; int b = i2 >> 5;
    float px = y_path[row*2], py = y_path[row*2+1];
    float2 out;
    if (cp < 16) {
        int u = 40 - (int)py; u = min(max(u,0), HH2-1);
        int v = (int)px;      v = min(max(v,0), HH2-1);
        out = *(const float2*)&g_fmap[((b*HH2+u)*HH2+v)*C2 + 2*cp];
    } else {
        int cc = 2*cp - 32;
        float pvx, pvy;
        if (t == 0) { pvx = cur_loc[i2*2]; pvy = cur_loc[i2*2+1]; }
        else { pvx = y_path[(row-BN)*2]; pvy = y_path[(row-BN)*2+1]; }
        float vx = (px-pvx)*10.f, vy = (py-pvy)*10.f;
        out.x = fvb[cc]   + vx*fvw[cc*2]   + vy*fvw[cc*2+1];
        out.y = fvb[cc+1] + vx*fvw[cc*2+2] + vy*fvw[cc*2+3];
    }
    *(float2*)&g_lhalf[(size_t)idx*2] = out;
}

// ---------------- single-counter grid barrier ----------------
__device__ __forceinline__ void gbar(unsigned target) {
    __syncthreads();
    if (threadIdx.x == 0) {
        unsigned old;
        asm volatile("atom.release.gpu.global.add.u32 %0, [%1], 1;"
                     : "=r"(old) : "l"(&g_bar_count) : "memory");
        if (old == NBLK - 1u) {
            g_bar_count = 0u;
            asm volatile("st.release.gpu.global.u32 [%0], %1;"
                         :: "l"(&g_bar_flag), "r"(target) : "memory");
        } else {
            unsigned v;
            do {
                __nanosleep(20);
                asm volatile("ld.acquire.gpu.global.u32 %0, [%1];"
                             : "=r"(v) : "l"(&g_bar_flag) : "memory");
            } while (v < target);
        }
    }
    __syncthreads();
}

// ---------------- persistent fused scan (1 barrier/step) ----------------
__global__ void __launch_bounds__(TSC, 1) scan_kernel(
        const float* __restrict__ hx,   const float* __restrict__ scfw,
        const float* __restrict__ whh,  const float* __restrict__ bhh,
        const float* __restrict__ wih,  const float* __restrict__ bih,
        const float* __restrict__ scfb, const float* __restrict__ scw) {
    extern __shared__ float sm[];
    float* sWT  = sm;              // 9216  Wscf og-slice (oo,hh,c)
    float* sWih = sm + 9216;       // 13920 (96 x 145)
    float* sWhh = sm + 23136;      // 6960  (48 x 145)
    float* sBi  = sm + 30096;      // 144
    float* sBh  = sm + 30240;      // 144
    float* sFb  = sm + 30384;      // 48
    float* sScw = sm + 30432;      // 48
    float* sHnT = sm + 30480;      // 1584 (48 x 33)
    float* sLT  = sm + 32064;      // 3168 (48 x 66) lhalf^T
    float* sRT  = sm + 35232;      // 3168 rhalf^T
    float* sBufA= sm + 38400;      // 3168 h^T ping
    float* sBufB= sm + 41568;      // 3168 h^T pong
    float2* sEnt = (float2*)(sm + 44736);  // 4096 fl (64 x 32 float2)
    int*   sCnt = (int*)(sm + 48832);      // 64
    float* sSc  = sm + 48896;      // 1536
    float* sScA = sm + 50432;      // 64 -> total 50496 fl

    int tid = threadIdx.x, blk = blockIdx.x;
    int bA = blk / 9, og = blk % 9;
    bool rowRole = (blk < 128);
    int r0 = blk * 64;
    int kq = r0 >> 9, i2b = r0 & 511;

    for (int i = tid; i < 9216; i += TSC) {
        int c = i % 48, rest = i / 48, hh = rest % 48, oo = rest / 48;
        sWT[oo*2304 + hh*48 + c] = scfw[c*1728 + (og*4+oo)*48 + hh];
    }
    for (int i = tid; i < 13824; i += TSC) {
        int c = i / 96, m = i % 96;
        sWih[m*145 + c] = wih[i];
    }
    for (int i = tid; i < 6912; i += TSC) {
        int c = i / 48, m = i % 48;
        sWhh[m*145 + c] = whh[i];
    }
    if (tid < 144) { sBi[tid] = bih[tid]; sBh[tid] = bhh[tid]; }
    if (tid < 48)  { sFb[tid] = scfb[tid]; sScw[tid] = scw[tid]; }
    if (tid < 64)  sScA[tid] = 0.f;
    float* pH = sBufA;
    float* pN = sBufB;
    if (rowRole)
        for (int i = tid; i < 3072; i += TSC) {
            int row = i / 48, c = i % 48;
            pH[c*66 + row] = hx[(i2b + row)*48 + c];
        }
    __syncthreads();

    unsigned bar = 0;
    for (int t = 0; t < TT; t++) {
        // ---- wait for h0(t) readiness (8 publishers per step) ----
        if (t > 0) {
            if (tid == 0) {
                unsigned v, tgt = 8u * (unsigned)t;
                for (;;) {
                    asm volatile("ld.acquire.gpu.global.u32 %0, [%1];"
                                 : "=r"(v) : "l"(&g_h0cnt) : "memory");
                    if (v >= tgt) break;
                    __nanosleep(20);
                }
            }
            __syncthreads();
        }
        // ---- h0 slice ----
        const float* hsrc = g_h0[t & 1] + bA*1536;
        for (int i = tid; i < 1536; i += TSC) {
            int n2 = i / 48, hh = i % 48;
            sHnT[hh*33 + n2] = __ldcg(hsrc + i);
        }
        __syncthreads();
        // ---- static loads for this step; land during HW compute ----
        int gb = 0;
        if (rowRole) {
            gb = (kq*TT + t)*BN + i2b;
            for (int i = tid; i < 3072; i += TSC) {
                int row = i / 48, c = i % 48;
                sLT[c*66 + row] = g_lhalf[(size_t)gb*48 + i];
            }
            if (tid < 64) {
                int cnt = g_cnt[gb + tid];
                sCnt[tid] = cnt;
                for (int e = 0; e < cnt; e++)
                    sEnt[tid*32 + e] = g_ent[(size_t)(gb + tid)*32 + e];
            }
        }
        // ---- HW table slice into buffer t&1 ----
        float* hw = g_HW[t & 1];
        for (int it = tid; it < 768; it += TSC) {
            int cg = it % 24, oo = (it/24) & 3, n2g = it / 96;
            float a0[4], a1[4];
            #pragma unroll
            for (int i = 0; i < 4; i++) { a0[i] = 0.f; a1[i] = 0.f; }
            const float* wt = sWT + oo*2304;
            for (int hh = 0; hh < 48; hh++) {
                float w0 = wt[hh*48 + cg], w1 = wt[hh*48 + cg + 24];
                #pragma unroll
                for (int i = 0; i < 4; i++) {
                    float hv = sHnT[hh*33 + n2g*4 + i];
                    a0[i] += hv*w0; a1[i] += hv*w1;
                }
            }
            #pragma unroll
            for (int i = 0; i < 4; i++) {
                int base = ((bA*NN + n2g*4+i)*NBIN + og*4 + oo)*48;
                hw[base + cg]      = a0[i];
                hw[base + cg + 24] = a1[i];
            }
        }
        gbar(++bar);
        if (rowRole) {
            // ---- gather ----
            for (int out = tid; out < 3072; out += TSC) {
                int lr = out / 48, c = out % 48;
                int cnt = sCnt[lr];
                float acc = sFb[c];
                const float* hwb = hw + ((i2b + lr) >> 5)*(NN*NBIN*48);
                for (int e = 0; e < cnt; e++) {
                    float2 en = sEnt[lr*32 + e];
                    acc += en.x * __ldcg(hwb + __float_as_int(en.y) + c);
                }
                sRT[c*66 + lr] = acc;
            }
            __syncthreads();
            // ---- fused f32x2 GEMM (4-row x 2-col tiles, 384 threads) ----
            if (tid < 384) {
                int cg = tid % 24, rg = tid / 24, rl = rg*4;
                ull gr2[2][2], gz2[2][2], gnx2[2][2], gnh2[2][2];
                #pragma unroll
                for (int jj = 0; jj < 2; jj++) {
                    int c = cg + 24*jj;
                    ull t0;
                    t0 = pk2(sBi[c]+sBh[c],       sBi[c]+sBh[c]);
                    gr2[0][jj] = t0; gr2[1][jj] = t0;
                    t0 = pk2(sBi[48+c]+sBh[48+c], sBi[48+c]+sBh[48+c]);
                    gz2[0][jj] = t0; gz2[1][jj] = t0;
                    t0 = pk2(sBi[96+c], sBi[96+c]);
                    gnx2[0][jj] = t0; gnx2[1][jj] = t0;
                    t0 = pk2(sBh[96+c], sBh[96+c]);
                    gnh2[0][jj] = t0; gnh2[1][jj] = t0;
                }
                #define SEG(XS, WP, NACC)                                      \
                for (int m = 0; m < 48; m++) {                                 \
                    ull x0 = *(const ull*)&XS[m*66 + rl];                      \
                    ull x1 = *(const ull*)&XS[m*66 + rl + 2];                  \
                    const float* wp = WP + m*145;                              \
                    _Pragma("unroll")                                          \
                    for (int jj = 0; jj < 2; jj++) {                           \
                        int c = cg + 24*jj;                                    \
                        ull wr = pk2(wp[c], wp[c]);                            \
                        ull wz = pk2(wp[48+c], wp[48+c]);                      \
                        ull wn = pk2(wp[96+c], wp[96+c]);                      \
                        fma2(gr2[0][jj], x0, wr); fma2(gr2[1][jj], x1, wr);    \
                        fma2(gz2[0][jj], x0, wz); fma2(gz2[1][jj], x1, wz);    \
                        fma2(NACC[0][jj], x0, wn); fma2(NACC[1][jj], x1, wn);  \
                    }                                                          \
                }
                SEG(sLT, sWih, gnx2)
                SEG((sRT), (sWih + 48*145), gnx2)
                SEG(pH, sWhh, gnh2)
                #undef SEG
                float scacc[4] = {0.f, 0.f, 0.f, 0.f};
                #pragma unroll
                for (int p = 0; p < 2; p++) {
                    #pragma unroll
                    for (int jj = 0; jj < 2; jj++) {
                        int c = cg + 24*jj;
                        float grl, grh, gzl, gzh, gxl, gxh, ghl, ghh;
                        upk2(gr2[p][jj],  grl, grh);
                        upk2(gz2[p][jj],  gzl, gzh);
                        upk2(gnx2[p][jj], gxl, gxh);
                        upk2(gnh2[p][jj], ghl, ghh);
                        int rowl = rl + 2*p, rowh = rowl + 1;
                        float r0f = sigf(grl), z0f = sigf(gzl);
                        float n0f = tanh_fast(gxl + r0f*ghl);
                        float h0f = (1.f - z0f)*n0f + z0f*pH[c*66 + rowl];
                        pN[c*66 + rowl] = h0f;
                        scacc[2*p]   += h0f * sScw[c];
                        float r1f = sigf(grh), z1f = sigf(gzh);
                        float n1f = tanh_fast(gxh + r1f*ghh);
                        float h1f = (1.f - z1f)*n1f + z1f*pH[c*66 + rowh];
                        pN[c*66 + rowh] = h1f;
                        scacc[2*p+1] += h1f * sScw[c];
                    }
                }
                #pragma unroll
                for (int i = 0; i < 4; i++) sSc[(rl+i)*24 + cg] = scacc[i];
            }
            __syncthreads();
            if (tid < 64) {
                float s = 0.f;
                #pragma unroll
                for (int c = 0; c < 24; c++) s += sSc[tid*24 + c];
                sScA[tid] += s;
            }
            if (blk < 8) {
                float* dst = g_h0[1 - (t & 1)] + r0*48;
                for (int i = tid; i < 3072; i += TSC) {
                    int row = i / 48, c = i % 48;
                    dst[i] = pN[c*66 + row];
                }
            }
        }
        // publish-visibility: sync whole block, then publishers signal
        __syncthreads();
        if (blk < 8 && tid == 0)
            asm volatile("red.release.gpu.global.add.u32 [%0], 1;"
                         :: "l"(&g_h0cnt) : "memory");
        { float* tmp = pH; pH = pN; pN = tmp; }
    }
    if (rowRole) {
        for (int i = tid; i < 3072; i += TSC) {
            int row = i / 48, c = i % 48;
            g_hfin[(size_t)r0*48 + i] = pH[c*66 + row];
        }
        if (tid < 64) g_score[r0 + tid] = sScA[tid];
    }
}

// ---------------- final ----------------
__global__ void final_kernel(const float* __restrict__ dyw,
                             const float* __restrict__ dyb,
                             const float* __restrict__ scb,
                             float* __restrict__ out) {
    int idx = blockIdx.x*256 + threadIdx.x;    // 663552
    if (idx < KBN*80) {
        int row = idx / 80, c = idx % 80;
        float acc = dyb[c];
        const float* hr = g_hfin + row*48;
        const float* w  = dyw + c*48;
        #pragma unroll 8
        for (int hh = 0; hh < 48; hh++) acc += hr[hh]*w[hh];
        int k = row >> 9, i2 = row & 511;
        int d = c / 40, tt = c % 40;
        out[((k*TT + tt)*BN + i2)*2 + d] = acc;
    } else {
        int row = idx - KBN*80;
        out[KBN*80 + row] = g_score[row] + 40.f*scb[0];
    }
}

// ---------------- launcher ----------------
extern "C" void kernel_launch(void* const* d_in, const int* in_sizes, int n_in,
                              void* d_out, int out_size) {
    const float* hx      = (const float*)d_in[0];
    const float* cur_loc = (const float*)d_in[1];
    const float* y_path  = (const float*)d_in[2];
    const float* image   = (const float*)d_in[3];
    const float* c1w     = (const float*)d_in[4];
    const float* c1b     = (const float*)d_in[5];
    const float* c2w     = (const float*)d_in[6];
    const float* c2b     = (const float*)d_in[7];
    const float* fvw     = (const float*)d_in[8];
    const float* fvb     = (const float*)d_in[9];
    const float* scfw    = (const float*)d_in[10];
    const float* scfb    = (const float*)d_in[11];
    const float* wih     = (const float*)d_in[12];
    const float* whh     = (const float*)d_in[13];
    const float* bih     = (const float*)d_in[14];
    const float* bhh     = (const float*)d_in[15];
    const float* dyw     = (const float*)d_in[16];
    const float* dyb     = (const float*)d_in[17];
    const float* scw     = (const float*)d_in[18];
    const float* scb     = (const float*)d_in[19];

    const int SMEM_SCAN = 50496 * 4;           // 201984 B
    cudaFuncSetAttribute(scan_kernel,
                         cudaFuncAttributeMaxDynamicSharedMemorySize, SMEM_SCAN);

    conv1x_kernel<<<7776, 256>>>(image, c1w, c1b, y_path, hx);
    conv2_kernel <<<1600, 128>>>(c2w, c2b);
    lhalf_kernel <<<30720,256>>>(y_path, cur_loc, fvw, fvb);
    scan_kernel  <<<NBLK, TSC, SMEM_SCAN>>>(hx, scfw, whh, bhh, wih, bih, scfb, scw);
    final_kernel <<<2592, 256>>>(dyw, dyb, scb, (float*)d_out);
}

// round 15
// speedup vs baseline: 1.1197x; 1.0290x over previous
#include <cuda_runtime.h>
#include <math.h>

#define KK 16
#define TT 40
#define BB 16
#define NN 32
#define BN 512
#define KBN 8192
#define HH2 80
#define C1 16
#define C2 32
#define NBIN 36
#define NBLK 144
#define TSC 512
#define HWSZ (BB*NN*NBIN*48)

typedef unsigned long long ull;

__device__ float g_conv1[BB*C1*HH2*HH2];
__device__ float g_fmap [BB*HH2*HH2*C2];
__device__ float g_lhalf[KK*TT*BN*48];
__device__ int   g_cnt[KK*TT*BN];
__device__ float2 g_ent[(size_t)KK*TT*BN*32];
__device__ float g_HW [2][HWSZ];
__device__ float g_h0 [2][BN*48];
__device__ float g_hfin[KBN*48];
__device__ float g_score[KBN];
__device__ unsigned g_bar_count;
__device__ unsigned g_bar_flag;
__device__ unsigned g_h0cnt;

// ---- f32x2 / fast-math helpers ----
__device__ __forceinline__ ull pk2(float lo, float hi) {
    ull r; asm("mov.b64 %0, {%1,%2};" : "=l"(r) : "f"(lo), "f"(hi)); return r;
}
__device__ __forceinline__ void upk2(ull v, float& lo, float& hi) {
    asm("mov.b64 {%0,%1}, %2;" : "=f"(lo), "=f"(hi) : "l"(v));
}
__device__ __forceinline__ void fma2(ull& a, ull x, ull y) {
    asm("fma.rn.f32x2 %0, %1, %2, %0;" : "+l"(a) : "l"(x), "l"(y));
}
__device__ __forceinline__ float sigf(float x) {
    float e; asm("ex2.approx.f32 %0, %1;" : "=f"(e) : "f"(x * -1.4426950408889634f));
    float r; asm("rcp.approx.f32 %0, %1;" : "=f"(r) : "f"(1.f + e));
    return r;
}
__device__ __forceinline__ float tanh_fast(float x) { return 2.f*sigf(2.f*x) - 1.f; }

// ---------------- bins helper ----------------
__device__ __forceinline__ int bin_of(float dx, float dy) {
    float dist = sqrtf(dx*dx + dy*dy);
    float dc = dist < 1e-10f ? 1e-10f : dist;
    float ct = acosf(fminf(fmaxf(dx/dc, -1.f), 1.f));
    float theta = (dy < -0.01f) ? (6.2831853071795864f - ct) : ct;
    const float R_STEP  = (float)(3.5/6.0);
    const float TH_STEP = (float)(6.283185307179586/6.0);
    int ub = (int)((dist - 0.5f)/R_STEP); ub = min(max(ub,0),5);
    int vb = (int)(theta/TH_STEP);        vb = min(max(vb,0),5);
    return ub*6 + vb;
}

// ---------------- conv1 + bins + init (merged) ----------------
__global__ void conv1x_kernel(const float* __restrict__ img,
                              const float* __restrict__ w,
                              const float* __restrict__ bias,
                              const float* __restrict__ y_path,
                              const float* __restrict__ hx) {
    __shared__ float sW[1600];
    __shared__ float sB[16];
    __shared__ float sP[8][NN][2];
    int blk = blockIdx.x, tid = threadIdx.x;
    if (blk < 6400) {
        for (int i = tid; i < 1600; i += 256) sW[i] = w[i];
        if (tid < 16) sB[tid] = bias[tid];
        __syncthreads();
        int idx = blk*256 + tid;
        int x = idx % HH2; int y = (idx/HH2) % HH2;
        int oc = (idx/(HH2*HH2)) % C1; int b = idx/(HH2*HH2*C1);
        float acc = sB[oc];
        for (int ic = 0; ic < 4; ic++)
            for (int ky = 0; ky < 5; ky++) {
                int iy = 2*y - 2 + ky;
                if (iy < 0 || iy >= 160) continue;
                const float* ip = img + ((b*4+ic)*160 + iy)*160;
                const float* wp = sW + (oc*4+ic)*25 + ky*5;
                #pragma unroll
                for (int kx = 0; kx < 5; kx++) {
                    int ix = 2*x - 2 + kx;
                    if (ix < 0 || ix >= 160) continue;
                    acc += ip[ix] * wp[kx];
                }
            }
        g_conv1[idx] = fmaxf(acc, 0.f);
    } else if (blk < 7680) {
        int g = tid >> 5, j = tid & 31;
        int grp = (blk - 6400)*8 + g;          // 10240 exact
        int b = grp % BB; int kt = grp / BB;
        int rowbase = kt*BN + b*NN;
        sP[g][j][0] = y_path[(rowbase+j)*2];
        sP[g][j][1] = y_path[(rowbase+j)*2+1];
        __syncwarp();
        float pjx = sP[g][j][0], pjy = sP[g][j][1];
        unsigned maskbits = 0;
        #pragma unroll
        for (int n2 = 0; n2 < NN; n2++) {
            float dx = sP[g][n2][0] - pjx;
            float dy = sP[g][n2][1] - pjy;
            float dist = sqrtf(dx*dx + dy*dy);
            if (n2 != j && dist >= 0.5f && dist <= 4.0f) maskbits |= 1u << n2;
        }
        size_t rowid = rowbase + j;
        int e = 0;
        unsigned m1 = maskbits;
        while (m1) {
            int n2 = __ffs(m1) - 1; m1 &= m1 - 1;
            int bn = bin_of(sP[g][n2][0]-pjx, sP[g][n2][1]-pjy);
            int cnt = 0;
            unsigned mq = maskbits;
            while (mq) {
                int q = __ffs(mq) - 1; mq &= mq - 1;
                cnt += (bin_of(sP[g][q][0]-pjx, sP[g][q][1]-pjy) == bn);
            }
            g_ent[rowid*32 + e] = make_float2(1.f/(float)cnt,
                                __int_as_float((n2*NBIN + bn)*48));
            e++;
        }
        g_cnt[rowid] = e;
    } else {
        int idx = (blk - 7680)*256 + tid;      // 24576 exact
        g_h0[0][idx] = hx[idx];
        if (idx == 0) { g_bar_count = 0u; g_bar_flag = 0u; g_h0cnt = 0u; }
    }
}

// ---------------- conv2 (f32x2) ----------------
__global__ void conv2_kernel(const float* __restrict__ w2,
                             const float* __restrict__ b2) {
    __shared__ float sIn[6400];
    __shared__ __align__(16) float sW[3200];
    int blk = blockIdx.x;                       // 1600
    int ocg = blk % 4; int tile = (blk/4) % 25; int b = blk/100;
    int ty0 = (tile/5)*16, tx0 = (tile%5)*16;
    int tid = threadIdx.x;                      // 128
    for (int i = tid; i < 6400; i += 128) {
        int ic = i/400; int rem = i%400; int ly = rem/20, lx = rem%20;
        int iy = ty0 + ly - 2, ix = tx0 + lx - 2;
        sIn[i] = (iy>=0 && iy<HH2 && ix>=0 && ix<HH2)
                 ? g_conv1[((b*C1+ic)*HH2+iy)*HH2+ix] : 0.f;
    }
    for (int i = tid; i < 3200; i += 128) {
        int ic = i/200, rem = i%200, k2 = rem/8, ocl = rem%8;
        sW[i] = w2[(ocg*8+ocl)*400 + ic*25 + k2];
    }
    __syncthreads();
    int tx = tid % 16, tyh = tid / 16;
    ull a0[4], a1[4];
    #pragma unroll
    for (int o2 = 0; o2 < 4; o2++) {
        a0[o2] = pk2(b2[ocg*8+2*o2], b2[ocg*8+2*o2+1]);
        a1[o2] = a0[o2];
    }
    for (int ic = 0; ic < 16; ic++) {
        float in0[25], in1[25];
        const float* p0 = sIn + ic*400 + tyh*20 + tx;
        const float* p1 = p0 + 160;
        #pragma unroll
        for (int ky = 0; ky < 5; ky++)
            #pragma unroll
            for (int kx = 0; kx < 5; kx++) {
                in0[ky*5+kx] = p0[ky*20+kx];
                in1[ky*5+kx] = p1[ky*20+kx];
            }
        #pragma unroll
        for (int k2 = 0; k2 < 25; k2++) {
            ull i0 = pk2(in0[k2], in0[k2]);
            ull i1 = pk2(in1[k2], in1[k2]);
            const float* wb = &sW[(ic*25+k2)*8];
            #pragma unroll
            for (int o2 = 0; o2 < 4; o2++) {
                ull w = *(const ull*)(wb + 2*o2);
                fma2(a0[o2], i0, w); fma2(a1[o2], i1, w);
            }
        }
    }
    #pragma unroll
    for (int o2 = 0; o2 < 4; o2++) {
        float v0, v1, u0, u1;
        upk2(a0[o2], v0, v1); upk2(a1[o2], u0, u1);
        int oc = ocg*8 + 2*o2;
        float* d0 = &g_fmap[((b*HH2 + ty0+tyh  )*HH2 + tx0+tx)*C2 + oc];
        float* d1 = &g_fmap[((b*HH2 + ty0+tyh+8)*HH2 + tx0+tx)*C2 + oc];
        d0[0] = fmaxf(v0, 0.f); d0[1] = fmaxf(v1, 0.f);
        d1[0] = fmaxf(u0, 0.f); d1[1] = fmaxf(u1, 0.f);
    }
}

// ---------------- lhalf ----------------
__global__ void lhalf_kernel(const float* __restrict__ y_path,
                             const float* __restrict__ cur_loc,
                             const float* __restrict__ fvw,
                             const float* __restrict__ fvb) {
    int idx = blockIdx.x*256 + threadIdx.x;    // 7,864,320
    int cp = idx % 24; int row = idx / 24;
    int kt = row / BN, i2 = row % BN;
    int t = kt % TT; int b = i2 >> 5;
    float px = y_path[row*2], py = y_path[row*2+1];
    float2 out;
    if (cp < 16) {
        int u = 40 - (int)py; u = min(max(u,0), HH2-1);
        int v = (int)px;      v = min(max(v,0), HH2-1);
        out = *(const float2*)&g_fmap[((b*HH2+u)*HH2+v)*C2 + 2*cp];
    } else {
        int cc = 2*cp - 32;
        float pvx, pvy;
        if (t == 0) { pvx = cur_loc[i2*2]; pvy = cur_loc[i2*2+1]; }
        else { pvx = y_path[(row-BN)*2]; pvy = y_path[(row-BN)*2+1]; }
        float vx = (px-pvx)*10.f, vy = (py-pvy)*10.f;
        out.x = fvb[cc]   + vx*fvw[cc*2]   + vy*fvw[cc*2+1];
        out.y = fvb[cc+1] + vx*fvw[cc*2+2] + vy*fvw[cc*2+3];
    }
    *(float2*)&g_lhalf[(size_t)idx*2] = out;
}

// ---------------- persistent fused scan (split-barrier pipeline) ----------
__global__ void __launch_bounds__(TSC, 1) scan_kernel(
        const float* __restrict__ hx,   const float* __restrict__ scfw,
        const float* __restrict__ whh,  const float* __restrict__ bhh,
        const float* __restrict__ wih,  const float* __restrict__ bih,
        const float* __restrict__ scfb, const float* __restrict__ scw) {
    extern __shared__ float sm[];
    float* sWT  = sm;              // 9216  Wscf og-slice (oo,hh,c)
    float* sWih = sm + 9216;       // 13920 (96 x 145)
    float* sWhh = sm + 23136;      // 6960  (48 x 145)
    float* sBi  = sm + 30096;      // 144
    float* sBh  = sm + 30240;      // 144
    float* sFb  = sm + 30384;      // 48
    float* sScw = sm + 30432;      // 48
    float* sHnT = sm + 30480;      // 1584 (48 x 33)
    float* sLT  = sm + 32064;      // 3168 (48 x 66) lhalf^T
    float* sRT  = sm + 35232;      // 3168 rhalf^T
    float* sBufA= sm + 38400;      // 3168 h^T ping
    float* sBufB= sm + 41568;      // 3168 h^T pong
    float2* sEnt = (float2*)(sm + 44736);  // 4096 fl (64 x 32 float2)
    int*   sCnt = (int*)(sm + 48832);      // 64
    float* sSc  = sm + 48896;      // 1536
    float* sScA = sm + 50432;      // 64 -> total 50496 fl

    int tid = threadIdx.x, blk = blockIdx.x;
    int bA = blk / 9, og = blk % 9;
    bool rowRole = (blk < 128);
    int r0 = blk * 64;
    int kq = r0 >> 9, i2b = r0 & 511;

    for (int i = tid; i < 9216; i += TSC) {
        int c = i % 48, rest = i / 48, hh = rest % 48, oo = rest / 48;
        sWT[oo*2304 + hh*48 + c] = scfw[c*1728 + (og*4+oo)*48 + hh];
    }
    for (int i = tid; i < 13824; i += TSC) {
        int c = i / 96, m = i % 96;
        sWih[m*145 + c] = wih[i];
    }
    for (int i = tid; i < 6912; i += TSC) {
        int c = i / 48, m = i % 48;
        sWhh[m*145 + c] = whh[i];
    }
    if (tid < 144) { sBi[tid] = bih[tid]; sBh[tid] = bhh[tid]; }
    if (tid < 48)  { sFb[tid] = scfb[tid]; sScw[tid] = scw[tid]; }
    if (tid < 64)  sScA[tid] = 0.f;
    float* pH = sBufA;
    float* pN = sBufB;
    if (rowRole)
        for (int i = tid; i < 3072; i += TSC) {
            int row = i / 48, c = i % 48;
            pH[c*66 + row] = hx[(i2b + row)*48 + c];
        }
    __syncthreads();

    for (int t = 0; t < TT; t++) {
        unsigned bar = (unsigned)(t + 1);
        // ---- wait for h0(t) readiness (8 publishers per step) ----
        if (t > 0) {
            if (tid == 0) {
                unsigned v, tgt = 8u * (unsigned)t;
                for (;;) {
                    asm volatile("ld.acquire.gpu.global.u32 %0, [%1];"
                                 : "=r"(v) : "l"(&g_h0cnt) : "memory");
                    if (v >= tgt) break;
                    __nanosleep(20);
                }
            }
            __syncthreads();
        }
        // ---- h0 slice ----
        const float* hsrc = g_h0[t & 1] + bA*1536;
        for (int i = tid; i < 1536; i += TSC) {
            int n2 = i / 48, hh = i % 48;
            sHnT[hh*33 + n2] = __ldcg(hsrc + i);
        }
        __syncthreads();
        // ---- static loads for this step; land during HW compute ----
        int gb = 0;
        if (rowRole) {
            gb = (kq*TT + t)*BN + i2b;
            for (int i = tid; i < 3072; i += TSC) {
                int row = i / 48, c = i % 48;
                sLT[c*66 + row] = g_lhalf[(size_t)gb*48 + i];
            }
            if (tid < 64) {
                int cnt = g_cnt[gb + tid];
                sCnt[tid] = cnt;
                for (int e = 0; e < cnt; e++)
                    sEnt[tid*32 + e] = g_ent[(size_t)(gb + tid)*32 + e];
            }
        }
        // ---- HW table slice into buffer t&1 ----
        float* hw = g_HW[t & 1];
        for (int it = tid; it < 768; it += TSC) {
            int cg = it % 24, oo = (it/24) & 3, n2g = it / 96;
            float a0[4], a1[4];
            #pragma unroll
            for (int i = 0; i < 4; i++) { a0[i] = 0.f; a1[i] = 0.f; }
            const float* wt = sWT + oo*2304;
            for (int hh = 0; hh < 48; hh++) {
                float w0 = wt[hh*48 + cg], w1 = wt[hh*48 + cg + 24];
                #pragma unroll
                for (int i = 0; i < 4; i++) {
                    float hv = sHnT[hh*33 + n2g*4 + i];
                    a0[i] += hv*w0; a1[i] += hv*w1;
                }
            }
            #pragma unroll
            for (int i = 0; i < 4; i++) {
                int base = ((bA*NN + n2g*4+i)*NBIN + og*4 + oo)*48;
                hw[base + cg]      = a0[i];
                hw[base + cg + 24] = a1[i];
            }
        }
        __syncthreads();   // HW stores done, sLT/sEnt visible
        // ---- barrier ARRIVE (thread 448, covers block's HW stores) ----
        if (tid == 448) {
            unsigned old;
            asm volatile("atom.release.gpu.global.add.u32 %0, [%1], 1;"
                         : "=r"(old) : "l"(&g_bar_count) : "memory");
            if (old == NBLK - 1u) {
                g_bar_count = 0u;
                asm volatile("st.release.gpu.global.u32 [%0], %1;"
                             :: "l"(&g_bar_flag), "r"(bar) : "memory");
            }
        }
        // ---- partial GEMM over lhalf + h segments (overlaps barrier wait) --
        ull gr2[2][2], gz2[2][2], gnx2[2][2], gnh2[2][2];
        int cg = tid % 24, rg = tid / 24, rl = rg*4;
        bool gemmT = rowRole && (tid < 384);
        if (gemmT) {
            #pragma unroll
            for (int jj = 0; jj < 2; jj++) {
                int c = cg + 24*jj;
                ull t0;
                t0 = pk2(sBi[c]+sBh[c],       sBi[c]+sBh[c]);
                gr2[0][jj] = t0; gr2[1][jj] = t0;
                t0 = pk2(sBi[48+c]+sBh[48+c], sBi[48+c]+sBh[48+c]);
                gz2[0][jj] = t0; gz2[1][jj] = t0;
                t0 = pk2(sBi[96+c], sBi[96+c]);
                gnx2[0][jj] = t0; gnx2[1][jj] = t0;
                t0 = pk2(sBh[96+c], sBh[96+c]);
                gnh2[0][jj] = t0; gnh2[1][jj] = t0;
            }
            #define SEG(XS, WP, NACC)                                          \
            for (int m = 0; m < 48; m++) {                                     \
                ull x0 = *(const ull*)&XS[m*66 + rl];                          \
                ull x1 = *(const ull*)&XS[m*66 + rl + 2];                      \
                const float* wp = WP + m*145;                                  \
                _Pragma("unroll")                                              \
                for (int jj = 0; jj < 2; jj++) {                               \
                    int c = cg + 24*jj;                                        \
                    ull wr = pk2(wp[c], wp[c]);                                \
                    ull wz = pk2(wp[48+c], wp[48+c]);                          \
                    ull wn = pk2(wp[96+c], wp[96+c]);                          \
                    fma2(gr2[0][jj], x0, wr); fma2(gr2[1][jj], x1, wr);        \
                    fma2(gz2[0][jj], x0, wz); fma2(gz2[1][jj], x1, wz);        \
                    fma2(NACC[0][jj], x0, wn); fma2(NACC[1][jj], x1, wn);      \
                }                                                              \
            }
            SEG(sLT, sWih, gnx2)
            SEG(pH, sWhh, gnh2)
        }
        // ---- barrier WAIT (thread 448 spins while others computed) ----
        if (tid == 448) {
            unsigned v;
            do {
                asm volatile("ld.acquire.gpu.global.u32 %0, [%1];"
                             : "=r"(v) : "l"(&g_bar_flag) : "memory");
            } while (v < bar);
        }
        __syncthreads();
        if (rowRole) {
            // ---- gather ----
            for (int out = tid; out < 3072; out += TSC) {
                int lr = out / 48, c = out % 48;
                int cnt = sCnt[lr];
                float acc = sFb[c];
                const float* hwb = hw + ((i2b + lr) >> 5)*(NN*NBIN*48);
                for (int e = 0; e < cnt; e++) {
                    float2 en = sEnt[lr*32 + e];
                    acc += en.x * __ldcg(hwb + __float_as_int(en.y) + c);
                }
                sRT[c*66 + lr] = acc;
            }
            __syncthreads();
            // ---- rhalf segment + GRU ----
            if (gemmT) {
                SEG((sRT), (sWih + 48*145), gnx2)
                #undef SEG
                float scacc[4] = {0.f, 0.f, 0.f, 0.f};
                #pragma unroll
                for (int p = 0; p < 2; p++) {
                    #pragma unroll
                    for (int jj = 0; jj < 2; jj++) {
                        int c = cg + 24*jj;
                        float grl, grh, gzl, gzh, gxl, gxh, ghl, ghh;
                        upk2(gr2[p][jj],  grl, grh);
                        upk2(gz2[p][jj],  gzl, gzh);
                        upk2(gnx2[p][jj], gxl, gxh);
                        upk2(gnh2[p][jj], ghl, ghh);
                        int rowl = rl + 2*p, rowh = rowl + 1;
                        float r0f = sigf(grl), z0f = sigf(gzl);
                        float n0f = tanh_fast(gxl + r0f*ghl);
                        float h0f = (1.f - z0f)*n0f + z0f*pH[c*66 + rowl];
                        pN[c*66 + rowl] = h0f;
                        scacc[2*p]   += h0f * sScw[c];
                        float r1f = sigf(grh), z1f = sigf(gzh);
                        float n1f = tanh_fast(gxh + r1f*ghh);
                        float h1f = (1.f - z1f)*n1f + z1f*pH[c*66 + rowh];
                        pN[c*66 + rowh] = h1f;
                        scacc[2*p+1] += h1f * sScw[c];
                    }
                }
                #pragma unroll
                for (int i = 0; i < 4; i++) sSc[(rl+i)*24 + cg] = scacc[i];
            }
            __syncthreads();
            if (tid < 64) {
                float s = 0.f;
                #pragma unroll
                for (int c = 0; c < 24; c++) s += sSc[tid*24 + c];
                sScA[tid] += s;
            }
            if (blk < 8) {
                float* dst = g_h0[1 - (t & 1)] + r0*48;
                for (int i = tid; i < 3072; i += TSC) {
                    int row = i / 48, c = i % 48;
                    dst[i] = pN[c*66 + row];
                }
            }
        }
        // publish-visibility: sync whole block, then publishers signal
        __syncthreads();
        if (blk < 8 && tid == 0)
            asm volatile("red.release.gpu.global.add.u32 [%0], 1;"
                         :: "l"(&g_h0cnt) : "memory");
        { float* tmp = pH; pH = pN; pN = tmp; }
    }
    if (rowRole) {
        for (int i = tid; i < 3072; i += TSC) {
            int row = i / 48, c = i % 48;
            g_hfin[(size_t)r0*48 + i] = pH[c*66 + row];
        }
        if (tid < 64) g_score[r0 + tid] = sScA[tid];
    }
}

// ---------------- final ----------------
__global__ void final_kernel(const float* __restrict__ dyw,
                             const float* __restrict__ dyb,
                             const float* __restrict__ scb,
                             float* __restrict__ out) {
    int idx = blockIdx.x*256 + threadIdx.x;    // 663552
    if (idx < KBN*80) {
        int row = idx / 80, c = idx % 80;
        float acc = dyb[c];
        const float* hr = g_hfin + row*48;
        const float* w  = dyw + c*48;
        #pragma unroll 8
        for (int hh = 0; hh < 48; hh++) acc += hr[hh]*w[hh];
        int k = row >> 9, i2 = row & 511;
        int d = c / 40, tt = c % 40;
        out[((k*TT + tt)*BN + i2)*2 + d] = acc;
    } else {
        int row = idx - KBN*80;
        out[KBN*80 + row] = g_score[row] + 40.f*scb[0];
    }
}

// ---------------- launcher ----------------
extern "C" void kernel_launch(void* const* d_in, const int* in_sizes, int n_in,
                              void* d_out, int out_size) {
    const float* hx      = (const float*)d_in[0];
    const float* cur_loc = (const float*)d_in[1];
    const float* y_path  = (const float*)d_in[2];
    const float* image   = (const float*)d_in[3];
    const float* c1w     = (const float*)d_in[4];
    const float* c1b     = (const float*)d_in[5];
    const float* c2w     = (const float*)d_in[6];
    const float* c2b     = (const float*)d_in[7];
    const float* fvw     = (const float*)d_in[8];
    const float* fvb     = (const float*)d_in[9];
    const float* scfw    = (const float*)d_in[10];
    const float* scfb    = (const float*)d_in[11];
    const float* wih     = (const float*)d_in[12];
    const float* whh     = (const float*)d_in[13];
    const float* bih     = (const float*)d_in[14];
    const float* bhh     = (const float*)d_in[15];
    const float* dyw     = (const float*)d_in[16];
    const float* dyb     = (const float*)d_in[17];
    const float* scw     = (const float*)d_in[18];
    const float* scb     = (const float*)d_in[19];

    const int SMEM_SCAN = 50496 * 4;           // 201984 B
    cudaFuncSetAttribute(scan_kernel,
                         cudaFuncAttributeMaxDynamicSharedMemorySize, SMEM_SCAN);

    conv1x_kernel<<<7776, 256>>>(image, c1w, c1b, y_path, hx);
    conv2_kernel <<<1600, 128>>>(c2w, c2b);
    lhalf_kernel <<<30720,256>>>(y_path, cur_loc, fvw, fvb);
    scan_kernel  <<<NBLK, TSC, SMEM_SCAN>>>(hx, scfw, whh, bhh, wih, bih, scfb, scw);
    final_kernel <<<2592, 256>>>(dyw, dyb, scb, (float*)d_out);
}

// round 16
// speedup vs baseline: 1.1497x; 1.0268x over previous
#include <cuda_runtime.h>
#include <math.h>

#define KK 16
#define TT 40
#define BB 16
#define NN 32
#define BN 512
#define KBN 8192
#define HH2 80
#define C1 16
#define C2 32
#define NBIN 36
#define NBLK 144
#define NBAR 136
#define TSC 512
#define HWSZ (BB*NN*NBIN*48)

typedef unsigned long long ull;

__device__ float g_conv1[BB*C1*HH2*HH2];
__device__ float g_fmap [BB*HH2*HH2*C2];
__device__ float g_lhalf[KK*TT*BN*48];
__device__ int   g_cnt[KK*TT*BN];
__device__ float2 g_ent[(size_t)KK*TT*BN*32];
__device__ float g_HW [2][HWSZ];
__device__ float g_h0 [2][BN*48];
__device__ float g_hfin[KBN*48];
__device__ float g_score[KBN];
__device__ unsigned g_bar_count;
__device__ unsigned g_bar_flag;
__device__ unsigned g_h0cnt;

// ---- f32x2 / fast-math helpers ----
__device__ __forceinline__ ull pk2(float lo, float hi) {
    ull r; asm("mov.b64 %0, {%1,%2};" : "=l"(r) : "f"(lo), "f"(hi)); return r;
}
__device__ __forceinline__ void upk2(ull v, float& lo, float& hi) {
    asm("mov.b64 {%0,%1}, %2;" : "=f"(lo), "=f"(hi) : "l"(v));
}
__device__ __forceinline__ void fma2(ull& a, ull x, ull y) {
    asm("fma.rn.f32x2 %0, %1, %2, %0;" : "+l"(a) : "l"(x), "l"(y));
}
__device__ __forceinline__ float sigf(float x) {
    float e; asm("ex2.approx.f32 %0, %1;" : "=f"(e) : "f"(x * -1.4426950408889634f));
    float r; asm("rcp.approx.f32 %0, %1;" : "=f"(r) : "f"(1.f + e));
    return r;
}
__device__ __forceinline__ float tanh_fast(float x) { return 2.f*sigf(2.f*x) - 1.f; }

// ---------------- bins helper ----------------
__device__ __forceinline__ int bin_of(float dx, float dy) {
    float dist = sqrtf(dx*dx + dy*dy);
    float dc = dist < 1e-10f ? 1e-10f : dist;
    float ct = acosf(fminf(fmaxf(dx/dc, -1.f), 1.f));
    float theta = (dy < -0.01f) ? (6.2831853071795864f - ct) : ct;
    const float R_STEP  = (float)(3.5/6.0);
    const float TH_STEP = (float)(6.283185307179586/6.0);
    int ub = (int)((dist - 0.5f)/R_STEP); ub = min(max(ub,0),5);
    int vb = (int)(theta/TH_STEP);        vb = min(max(vb,0),5);
    return ub*6 + vb;
}

// ---------------- conv1 + bins + init (merged) ----------------
__global__ void conv1x_kernel(const float* __restrict__ img,
                              const float* __restrict__ w,
                              const float* __restrict__ bias,
                              const float* __restrict__ y_path,
                              const float* __restrict__ hx) {
    __shared__ float sW[1600];
    __shared__ float sB[16];
    __shared__ float sP[8][NN][2];
    int blk = blockIdx.x, tid = threadIdx.x;
    if (blk < 6400) {
        for (int i = tid; i < 1600; i += 256) sW[i] = w[i];
        if (tid < 16) sB[tid] = bias[tid];
        __syncthreads();
        int idx = blk*256 + tid;
        int x = idx % HH2; int y = (idx/HH2) % HH2;
        int oc = (idx/(HH2*HH2)) % C1; int b = idx/(HH2*HH2*C1);
        float acc = sB[oc];
        for (int ic = 0; ic < 4; ic++)
            for (int ky = 0; ky < 5; ky++) {
                int iy = 2*y - 2 + ky;
                if (iy < 0 || iy >= 160) continue;
                const float* ip = img + ((b*4+ic)*160 + iy)*160;
                const float* wp = sW + (oc*4+ic)*25 + ky*5;
                #pragma unroll
                for (int kx = 0; kx < 5; kx++) {
                    int ix = 2*x - 2 + kx;
                    if (ix < 0 || ix >= 160) continue;
                    acc += ip[ix] * wp[kx];
                }
            }
        g_conv1[idx] = fmaxf(acc, 0.f);
    } else if (blk < 7680) {
        int g = tid >> 5, j = tid & 31;
        int grp = (blk - 6400)*8 + g;          // 10240 exact
        int b = grp % BB; int kt = grp / BB;
        int rowbase = kt*BN + b*NN;
        sP[g][j][0] = y_path[(rowbase+j)*2];
        sP[g][j][1] = y_path[(rowbase+j)*2+1];
        __syncwarp();
        float pjx = sP[g][j][0], pjy = sP[g][j][1];
        unsigned maskbits = 0;
        #pragma unroll
        for (int n2 = 0; n2 < NN; n2++) {
            float dx = sP[g][n2][0] - pjx;
            float dy = sP[g][n2][1] - pjy;
            float dist = sqrtf(dx*dx + dy*dy);
            if (n2 != j && dist >= 0.5f && dist <= 4.0f) maskbits |= 1u << n2;
        }
        size_t rowid = rowbase + j;
        int e = 0;
        unsigned m1 = maskbits;
        while (m1) {
            int n2 = __ffs(m1) - 1; m1 &= m1 - 1;
            int bn = bin_of(sP[g][n2][0]-pjx, sP[g][n2][1]-pjy);
            int cnt = 0;
            unsigned mq = maskbits;
            while (mq) {
                int q = __ffs(mq) - 1; mq &= mq - 1;
                cnt += (bin_of(sP[g][q][0]-pjx, sP[g][q][1]-pjy) == bn);
            }
            g_ent[rowid*32 + e] = make_float2(1.f/(float)cnt,
                                __int_as_float((n2*NBIN + bn)*48));
            e++;
        }
        g_cnt[rowid] = e;
    } else {
        int idx = (blk - 7680)*256 + tid;      // 24576 exact
        g_h0[0][idx] = hx[idx];
        if (idx == 0) { g_bar_count = 0u; g_bar_flag = 0u; g_h0cnt = 0u; }
    }
}

// ---------------- conv2 (f32x2) ----------------
__global__ void conv2_kernel(const float* __restrict__ w2,
                             const float* __restrict__ b2) {
    __shared__ float sIn[6400];
    __shared__ __align__(16) float sW[3200];
    int blk = blockIdx.x;                       // 1600
    int ocg = blk % 4; int tile = (blk/4) % 25; int b = blk/100;
    int ty0 = (tile/5)*16, tx0 = (tile%5)*16;
    int tid = threadIdx.x;                      // 128
    for (int i = tid; i < 6400; i += 128) {
        int ic = i/400; int rem = i%400; int ly = rem/20, lx = rem%20;
        int iy = ty0 + ly - 2, ix = tx0 + lx - 2;
        sIn[i] = (iy>=0 && iy<HH2 && ix>=0 && ix<HH2)
                 ? g_conv1[((b*C1+ic)*HH2+iy)*HH2+ix] : 0.f;
    }
    for (int i = tid; i < 3200; i += 128) {
        int ic = i/200, rem = i%200, k2 = rem/8, ocl = rem%8;
        sW[i] = w2[(ocg*8+ocl)*400 + ic*25 + k2];
    }
    __syncthreads();
    int tx = tid % 16, tyh = tid / 16;
    ull a0[4], a1[4];
    #pragma unroll
    for (int o2 = 0; o2 < 4; o2++) {
        a0[o2] = pk2(b2[ocg*8+2*o2], b2[ocg*8+2*o2+1]);
        a1[o2] = a0[o2];
    }
    for (int ic = 0; ic < 16; ic++) {
        float in0[25], in1[25];
        const float* p0 = sIn + ic*400 + tyh*20 + tx;
        const float* p1 = p0 + 160;
        #pragma unroll
        for (int ky = 0; ky < 5; ky++)
            #pragma unroll
            for (int kx = 0; kx < 5; kx++) {
                in0[ky*5+kx] = p0[ky*20+kx];
                in1[ky*5+kx] = p1[ky*20+kx];
            }
        #pragma unroll
        for (int k2 = 0; k2 < 25; k2++) {
            ull i0 = pk2(in0[k2], in0[k2]);
            ull i1 = pk2(in1[k2], in1[k2]);
            const float* wb = &sW[(ic*25+k2)*8];
            #pragma unroll
            for (int o2 = 0; o2 < 4; o2++) {
                ull w = *(const ull*)(wb + 2*o2);
                fma2(a0[o2], i0, w); fma2(a1[o2], i1, w);
            }
        }
    }
    #pragma unroll
    for (int o2 = 0; o2 < 4; o2++) {
        float v0, v1, u0, u1;
        upk2(a0[o2], v0, v1); upk2(a1[o2], u0, u1);
        int oc = ocg*8 + 2*o2;
        float* d0 = &g_fmap[((b*HH2 + ty0+tyh  )*HH2 + tx0+tx)*C2 + oc];
        float* d1 = &g_fmap[((b*HH2 + ty0+tyh+8)*HH2 + tx0+tx)*C2 + oc];
        d0[0] = fmaxf(v0, 0.f); d0[1] = fmaxf(v1, 0.f);
        d1[0] = fmaxf(u0, 0.f); d1[1] = fmaxf(u1, 0.f);
    }
}

// ---------------- lhalf ----------------
__global__ void lhalf_kernel(const float* __restrict__ y_path,
                             const float* __restrict__ cur_loc,
                             const float* __restrict__ fvw,
                             const float* __restrict__ fvb) {
    int idx = blockIdx.x*256 + threadIdx.x;    // 7,864,320
    int cp = idx % 24; int row = idx / 24;
    int kt = row / BN, i2 = row % BN;
    int t = kt % TT; int b = i2 >> 5;
    float px = y_path[row*2], py = y_path[row*2+1];
    float2 out;
    if (cp < 16) {
        int u = 40 - (int)py; u = min(max(u,0), HH2-1);
        int v = (int)px;      v = min(max(v,0), HH2-1);
        out = *(const float2*)&g_fmap[((b*HH2+u)*HH2+v)*C2 + 2*cp];
    } else {
        int cc = 2*cp - 32;
        float pvx, pvy;
        if (t == 0) { pvx = cur_loc[i2*2]; pvy = cur_loc[i2*2+1]; }
        else { pvx = y_path[(row-BN)*2]; pvy = y_path[(row-BN)*2+1]; }
        float vx = (px-pvx)*10.f, vy = (py-pvy)*10.f;
        out.x = fvb[cc]   + vx*fvw[cc*2]   + vy*fvw[cc*2+1];
        out.y = fvb[cc+1] + vx*fvw[cc*2+2] + vy*fvw[cc*2+3];
    }
    *(float2*)&g_lhalf[(size_t)idx*2] = out;
}

// ---------------- HW slice routine ----------------
__device__ __forceinline__ void hw_slice(const float* __restrict__ sWTp,
                                         const float* __restrict__ sHnTp,
                                         float* __restrict__ hw,
                                         int bA, int og, int tid) {
    for (int it = tid; it < 768; it += TSC) {
        int cg = it % 24, oo = (it/24) & 3, n2g = it / 96;
        float a0[4], a1[4];
        #pragma unroll
        for (int i = 0; i < 4; i++) { a0[i] = 0.f; a1[i] = 0.f; }
        const float* wt = sWTp + oo*2304;
        for (int hh = 0; hh < 48; hh++) {
            float w0 = wt[hh*48 + cg], w1 = wt[hh*48 + cg + 24];
            #pragma unroll
            for (int i = 0; i < 4; i++) {
                float hv = sHnTp[hh*33 + n2g*4 + i];
                a0[i] += hv*w0; a1[i] += hv*w1;
            }
        }
        #pragma unroll
        for (int i = 0; i < 4; i++) {
            int base = ((bA*NN + n2g*4+i)*NBIN + og*4 + oo)*48;
            hw[base + cg]      = a0[i];
            hw[base + cg + 24] = a1[i];
        }
    }
}

// ---------------- persistent fused scan (role-specialized) ----------------
__global__ void __launch_bounds__(TSC, 1) scan_kernel(
        const float* __restrict__ hx,   const float* __restrict__ scfw,
        const float* __restrict__ whh,  const float* __restrict__ bhh,
        const float* __restrict__ wih,  const float* __restrict__ bih,
        const float* __restrict__ scfb, const float* __restrict__ scw) {
    extern __shared__ float sm[];
    float* sWT  = sm;              // 9216  Wscf og-slice (oo,hh,c)
    float* sWih = sm + 9216;       // 13920 (96 x 145)
    float* sWhh = sm + 23136;      // 6960  (48 x 145)
    float* sBi  = sm + 30096;      // 144
    float* sBh  = sm + 30240;      // 144
    float* sFb  = sm + 30384;      // 48
    float* sScw = sm + 30432;      // 48
    float* sHnT = sm + 30480;      // 1584 (48 x 33)
    float* sLT  = sm + 32064;      // 3168 (48 x 66) lhalf^T
    float* sRT  = sm + 35232;      // 3168 rhalf^T
    float* sBufA= sm + 38400;      // 3168 h^T ping
    float* sBufB= sm + 41568;      // 3168 h^T pong
    float2* sEnt = (float2*)(sm + 44736);  // 4096 fl (64 x 32 float2)
    int*   sCnt = (int*)(sm + 48832);      // 64
    float* sSc  = sm + 48896;      // 1536
    float* sScA = sm + 50432;      // 64 -> total 50496 fl
    // aliases for HW-only blocks (128..143): row-role regions unused there
    float* sWT2  = sm + 32064;     // 9216 (aliases sLT/sRT)
    float* sHnT2 = sm + 41280;     // 1584 (aliases sBufA/B tail)

    int tid = threadIdx.x, blk = blockIdx.x;
    bool isPub = (blk < 8);
    bool rowRole = (blk < 128);
    int r0 = blk * 64;
    int kq = r0 >> 9, i2b = r0 & 511;

    // HW pair assignment (blocks 8..143 only)
    int p1 = -1, p2 = -1;
    if (blk >= 8) {
        p1 = (blk < 128) ? (blk - 8) : (120 + (blk - 128));
        if (blk >= 128 && blk < 136) p2 = 136 + (blk - 128);
    }
    int bA1 = p1 >= 0 ? p1/9 : 0, og1 = p1 >= 0 ? p1%9 : 0;
    int bA2 = p2 >= 0 ? p2/9 : 0, og2 = p2 >= 0 ? p2%9 : 0;

    if (p1 >= 0)
        for (int i = tid; i < 9216; i += TSC) {
            int c = i % 48, rest = i / 48, hh = rest % 48, oo = rest / 48;
            sWT[oo*2304 + hh*48 + c] = scfw[c*1728 + (og1*4+oo)*48 + hh];
        }
    if (p2 >= 0)
        for (int i = tid; i < 9216; i += TSC) {
            int c = i % 48, rest = i / 48, hh = rest % 48, oo = rest / 48;
            sWT2[oo*2304 + hh*48 + c] = scfw[c*1728 + (og2*4+oo)*48 + hh];
        }
    for (int i = tid; i < 13824; i += TSC) {
        int c = i / 96, m = i % 96;
        sWih[m*145 + c] = wih[i];
    }
    for (int i = tid; i < 6912; i += TSC) {
        int c = i / 48, m = i % 48;
        sWhh[m*145 + c] = whh[i];
    }
    if (tid < 144) { sBi[tid] = bih[tid]; sBh[tid] = bhh[tid]; }
    if (tid < 48)  { sFb[tid] = scfb[tid]; sScw[tid] = scw[tid]; }
    if (tid < 64)  sScA[tid] = 0.f;
    float* pH = sBufA;
    float* pN = sBufB;
    if (rowRole)
        for (int i = tid; i < 3072; i += TSC) {
            int row = i / 48, c = i % 48;
            pH[c*66 + row] = hx[(i2b + row)*48 + c];
        }
    __syncthreads();

    for (int t = 0; t < TT; t++) {
        unsigned bar = (unsigned)(t + 1);
        // ---- non-pubs: wait h0(t) readiness ----
        if (!isPub && t > 0) {
            if (tid == 0) {
                unsigned v, tgt = 8u * (unsigned)t;
                for (;;) {
                    asm volatile("ld.acquire.gpu.global.u32 %0, [%1];"
                                 : "=r"(v) : "l"(&g_h0cnt) : "memory");
                    if (v >= tgt) break;
                    __nanosleep(20);
                }
            }
            __syncthreads();
        }
        // ---- h0 slices (non-pubs) ----
        if (!isPub) {
            const float* hs1 = g_h0[t & 1] + bA1*1536;
            for (int i = tid; i < 1536; i += TSC) {
                int n2 = i / 48, hh = i % 48;
                sHnT[hh*33 + n2] = __ldcg(hs1 + i);
            }
            if (p2 >= 0) {
                const float* hs2 = g_h0[t & 1] + bA2*1536;
                for (int i = tid; i < 1536; i += TSC) {
                    int n2 = i / 48, hh = i % 48;
                    sHnT2[hh*33 + n2] = __ldcg(hs2 + i);
                }
            }
        }
        // ---- row blocks: issue static loads ----
        int gb = 0;
        if (rowRole) {
            gb = (kq*TT + t)*BN + i2b;
            for (int i = tid; i < 3072; i += TSC) {
                int row = i / 48, c = i % 48;
                sLT[c*66 + row] = g_lhalf[(size_t)gb*48 + i];
            }
            if (tid < 64) {
                int cnt = g_cnt[gb + tid];
                sCnt[tid] = cnt;
                for (int e = 0; e < cnt; e++)
                    sEnt[tid*32 + e] = g_ent[(size_t)(gb + tid)*32 + e];
            }
        }
        __syncthreads();
        // ---- HW (non-pubs) + arrive ----
        float* hw = g_HW[t & 1];
        if (!isPub) {
            hw_slice(sWT, sHnT, hw, bA1, og1, tid);
            if (p2 >= 0) hw_slice(sWT2, sHnT2, hw, bA2, og2, tid);
            __syncthreads();
            if (tid == 448) {
                unsigned old;
                asm volatile("atom.release.gpu.global.add.u32 %0, [%1], 1;"
                             : "=r"(old) : "l"(&g_bar_count) : "memory");
                if (old == NBAR - 1u) {
                    g_bar_count = 0u;
                    asm volatile("st.release.gpu.global.u32 [%0], %1;"
                                 :: "l"(&g_bar_flag), "r"(bar) : "memory");
                }
            }
        }
        // ---- partial GEMM over lhalf + h segments (overlaps barrier) ----
        ull gr2[2][2], gz2[2][2], gnx2[2][2], gnh2[2][2];
        int cg = tid % 24, rg = tid / 24, rl = rg*4;
        bool gemmT = rowRole && (tid < 384);
        if (gemmT) {
            #pragma unroll
            for (int jj = 0; jj < 2; jj++) {
                int c = cg + 24*jj;
                ull t0;
                t0 = pk2(sBi[c]+sBh[c],       sBi[c]+sBh[c]);
                gr2[0][jj] = t0; gr2[1][jj] = t0;
                t0 = pk2(sBi[48+c]+sBh[48+c], sBi[48+c]+sBh[48+c]);
                gz2[0][jj] = t0; gz2[1][jj] = t0;
                t0 = pk2(sBi[96+c], sBi[96+c]);
                gnx2[0][jj] = t0; gnx2[1][jj] = t0;
                t0 = pk2(sBh[96+c], sBh[96+c]);
                gnh2[0][jj] = t0; gnh2[1][jj] = t0;
            }
            #define SEG(XS, WP, NACC)                                          \
            for (int m = 0; m < 48; m++) {                                     \
                ull x0 = *(const ull*)&XS[m*66 + rl];                          \
                ull x1 = *(const ull*)&XS[m*66 + rl + 2];                      \
                const float* wp = WP + m*145;                                  \
                _Pragma("unroll")                                              \
                for (int jj = 0; jj < 2; jj++) {                               \
                    int c = cg + 24*jj;                                        \
                    ull wr = pk2(wp[c], wp[c]);                                \
                    ull wz = pk2(wp[48+c], wp[48+c]);                          \
                    ull wn = pk2(wp[96+c], wp[96+c]);                          \
                    fma2(gr2[0][jj], x0, wr); fma2(gr2[1][jj], x1, wr);        \
                    fma2(gz2[0][jj], x0, wz); fma2(gz2[1][jj], x1, wz);        \
                    fma2(NACC[0][jj], x0, wn); fma2(NACC[1][jj], x1, wn);      \
                }                                                              \
            }
            SEG(sLT, sWih, gnx2)
            SEG(pH, sWhh, gnh2)
        }
        // ---- barrier WAIT (thread 448 spins; pubs spin hard) ----
        if (tid == 448) {
            unsigned v;
            do {
                asm volatile("ld.acquire.gpu.global.u32 %0, [%1];"
                             : "=r"(v) : "l"(&g_bar_flag) : "memory");
            } while (v < bar);
        }
        __syncthreads();
        if (rowRole) {
            // ---- gather ----
            for (int out = tid; out < 3072; out += TSC) {
                int lr = out / 48, c = out % 48;
                int cnt = sCnt[lr];
                float acc = sFb[c];
                const float* hwb = hw + ((i2b + lr) >> 5)*(NN*NBIN*48);
                for (int e = 0; e < cnt; e++) {
                    float2 en = sEnt[lr*32 + e];
                    acc += en.x * __ldcg(hwb + __float_as_int(en.y) + c);
                }
                sRT[c*66 + lr] = acc;
            }
            __syncthreads();
            // ---- rhalf segment + GRU ----
            if (gemmT) {
                SEG((sRT), (sWih + 48*145), gnx2)
                #undef SEG
                float scacc[4] = {0.f, 0.f, 0.f, 0.f};
                #pragma unroll
                for (int p = 0; p < 2; p++) {
                    #pragma unroll
                    for (int jj = 0; jj < 2; jj++) {
                        int c = cg + 24*jj;
                        float grl, grh, gzl, gzh, gxl, gxh, ghl, ghh;
                        upk2(gr2[p][jj],  grl, grh);
                        upk2(gz2[p][jj],  gzl, gzh);
                        upk2(gnx2[p][jj], gxl, gxh);
                        upk2(gnh2[p][jj], ghl, ghh);
                        int rowl = rl + 2*p, rowh = rowl + 1;
                        float r0f = sigf(grl), z0f = sigf(gzl);
                        float n0f = tanh_fast(gxl + r0f*ghl);
                        float h0f = (1.f - z0f)*n0f + z0f*pH[c*66 + rowl];
                        pN[c*66 + rowl] = h0f;
                        scacc[2*p]   += h0f * sScw[c];
                        float r1f = sigf(grh), z1f = sigf(gzh);
                        float n1f = tanh_fast(gxh + r1f*ghh);
                        float h1f = (1.f - z1f)*n1f + z1f*pH[c*66 + rowh];
                        pN[c*66 + rowh] = h1f;
                        scacc[2*p+1] += h1f * sScw[c];
                    }
                }
                #pragma unroll
                for (int i = 0; i < 4; i++) sSc[(rl+i)*24 + cg] = scacc[i];
            }
            __syncthreads();
            if (tid < 64) {
                float s = 0.f;
                #pragma unroll
                for (int c = 0; c < 24; c++) s += sSc[tid*24 + c];
                sScA[tid] += s;
            }
            if (isPub) {
                float* dst = g_h0[1 - (t & 1)] + r0*48;
                for (int i = tid; i < 3072; i += TSC) {
                    int row = i / 48, c = i % 48;
                    dst[i] = pN[c*66 + row];
                }
            }
        }
        // publish-visibility: sync whole block, then publishers signal
        __syncthreads();
        if (isPub && tid == 0)
            asm volatile("red.release.gpu.global.add.u32 [%0], 1;"
                         :: "l"(&g_h0cnt) : "memory");
        { float* tmp = pH; pH = pN; pN = tmp; }
    }
    if (rowRole) {
        for (int i = tid; i < 3072; i += TSC) {
            int row = i / 48, c = i % 48;
            g_hfin[(size_t)r0*48 + i] = pH[c*66 + row];
        }
        if (tid < 64) g_score[r0 + tid] = sScA[tid];
    }
}

// ---------------- final ----------------
__global__ void final_kernel(const float* __restrict__ dyw,
                             const float* __restrict__ dyb,
                             const float* __restrict__ scb,
                             float* __restrict__ out) {
    int idx = blockIdx.x*256 + threadIdx.x;    // 663552
    if (idx < KBN*80) {
        int row = idx / 80, c = idx % 80;
        float acc = dyb[c];
        const float* hr = g_hfin + row*48;
        const float* w  = dyw + c*48;
        #pragma unroll 8
        for (int hh = 0; hh < 48; hh++) acc += hr[hh]*w[hh];
        int k = row >> 9, i2 = row & 511;
        int d = c / 40, tt = c % 40;
        out[((k*TT + tt)*BN + i2)*2 + d] = acc;
    } else {
        int row = idx - KBN*80;
        out[KBN*80 + row] = g_score[row] + 40.f*scb[0];
    }
}

// ---------------- launcher ----------------
extern "C" void kernel_launch(void* const* d_in, const int* in_sizes, int n_in,
                              void* d_out, int out_size) {
    const float* hx      = (const float*)d_in[0];
    const float* cur_loc = (const float*)d_in[1];
    const float* y_path  = (const float*)d_in[2];
    const float* image   = (const float*)d_in[3];
    const float* c1w     = (const float*)d_in[4];
    const float* c1b     = (const float*)d_in[5];
    const float* c2w     = (const float*)d_in[6];
    const float* c2b     = (const float*)d_in[7];
    const float* fvw     = (const float*)d_in[8];
    const float* fvb     = (const float*)d_in[9];
    const float* scfw    = (const float*)d_in[10];
    const float* scfb    = (const float*)d_in[11];
    const float* wih     = (const float*)d_in[12];
    const float* whh     = (const float*)d_in[13];
    const float* bih     = (const float*)d_in[14];
    const float* bhh     = (const float*)d_in[15];
    const float* dyw     = (const float*)d_in[16];
    const float* dyb     = (const float*)d_in[17];
    const float* scw     = (const float*)d_in[18];
    const float* scb     = (const float*)d_in[19];

    const int SMEM_SCAN = 50496 * 4;           // 201984 B
    cudaFuncSetAttribute(scan_kernel,
                         cudaFuncAttributeMaxDynamicSharedMemorySize, SMEM_SCAN);

    conv1x_kernel<<<7776, 256>>>(image, c1w, c1b, y_path, hx);
    conv2_kernel <<<1600, 128>>>(c2w, c2b);
    lhalf_kernel <<<30720,256>>>(y_path, cur_loc, fvw, fvb);
    scan_kernel  <<<NBLK, TSC, SMEM_SCAN>>>(hx, scfw, whh, bhh, wih, bih, scfb, scw);
    final_kernel <<<2592, 256>>>(dyw, dyb, scb, (float*)d_out);
}